// round 10
// baseline (speedup 1.0000x reference)
#include <cuda_runtime.h>
#include <cuda_fp16.h>
#include <cstdint>

#define HH 256
#define WW 256
#define BB 16
#define CC 32
#define OO 32
#define TR 16
#define TC 32

#define ROWS 30                      // tile y: exact reach 16 + (-7..+13)
#define COLS 46                      // tile x: exact reach
#define PXH 32                       // halfs per pixel (32 channels)
#define TILE_BYTES (ROWS * COLS * 64)            // 88320
#define SWF_OFF  TILE_BYTES
#define SWF_BYTES (9 * 32 * 2 * 4 * 8)           // 18432: [tap][och][ks][tig] ull
#define GEOM_OFF (SWF_OFF + SWF_BYTES)           // 106752
#define SMEM_DYN (GEOM_OFF + 9 * 32)             // 107040 (2 CTAs/SM)

// blur dynamic smem: tile2 (36*36 ull) + hbuf (36*32 ull) + obuf (8*1024 half2)
#define B_TILE2_ULL (36 * 36)
#define B_HBUF_ULL  (36 * 32)
#define B_OBUF_OFF  ((B_TILE2_ULL + B_HBUF_ULL) * 8)     // 19584
#define B_SMEM_DYN  (B_OBUF_OFF + 8 * 1024 * 4)          // 52352

// g_blur: [b][y][x][32 ch] halfs
__device__ __half g_blur[(size_t)BB * HH * WW * 32];
__device__ __half g_wprep[9 * 32 * 2 * 4 * 4];   // ull layout [tap][och][ks][tig]

typedef unsigned long long ull;

__device__ __forceinline__ ull pack2(float lo, float hi) {
    ull r; asm("mov.b64 %0, {%1, %2};" : "=l"(r) : "f"(lo), "f"(hi)); return r;
}
__device__ __forceinline__ void unpack2(ull v, float& lo, float& hi) {
    asm("mov.b64 {%0, %1}, %2;" : "=f"(lo), "=f"(hi) : "l"(v));
}
__device__ __forceinline__ ull fma2(ull a, ull b, ull c) {
    ull d; asm("fma.rn.f32x2 %0, %1, %2, %3;" : "=l"(d) : "l"(a), "l"(b), "l"(c));
    return d;
}
__device__ __forceinline__ ull mul2(ull a, ull b) {
    ull d; asm("mul.rn.f32x2 %0, %1, %2;" : "=l"(d) : "l"(a), "l"(b)); return d;
}
__device__ __forceinline__ uint32_t s2u(const void* p) {
    uint32_t a;
    asm("{ .reg .u64 t; cvta.to.shared.u64 t, %1; cvt.u32.u64 %0, t; }"
        : "=r"(a) : "l"(p));
    return a;
}
__device__ __forceinline__ void cpasync16(uint32_t dst, const void* src, int sz) {
    asm volatile("cp.async.cg.shared.global [%0], [%1], 16, %2;"
                 :: "r"(dst), "l"(src), "r"(sz) : "memory");
}
__device__ __forceinline__ void mma_f16(float* d, uint32_t a0, uint32_t a1,
                                        uint32_t a2, uint32_t a3,
                                        uint32_t b0, uint32_t b1) {
    asm volatile(
        "mma.sync.aligned.m16n8k16.row.col.f32.f16.f16.f32 "
        "{%0,%1,%2,%3}, {%4,%5,%6,%7}, {%8,%9}, {%0,%1,%2,%3};"
        : "+f"(d[0]), "+f"(d[1]), "+f"(d[2]), "+f"(d[3])
        : "r"(a0), "r"(a1), "r"(a2), "r"(a3), "r"(b0), "r"(b1));
}

// --------- Kernel 1: separable 5x5 blur + folded weight prep -----------------------
// grid (8,8,BB*2): z = b*2 + g16, handles channels g16*16..+15 of batch b.
// Blocks with x==0,y==0 also prep weights (9216 elems over 32 z-blocks).
__global__ __launch_bounds__(256) void blur_kernel(const float* __restrict__ x,
                                                   const float* __restrict__ sigp,
                                                   const float* __restrict__ w) {
    extern __shared__ __align__(16) char bsm[];
    ull* tile2 = (ull*)bsm;                          // [36][36]
    ull* hbuf = tile2 + B_TILE2_ULL;                 // [36][32]
    __half2* obuf = (__half2*)(bsm + B_OBUF_OFF);    // [8 pair][1024 px]

    const int tid = threadIdx.x + threadIdx.y * 32;
    const int z = blockIdx.z;

    // folded weight prep: [o][c][k] -> ull layout [k][o][s=c>>4][tig=(c&15)>>2][j]
    if (blockIdx.x == 0 && blockIdx.y == 0) {
        for (int t = z * 288 + tid; t < (z + 1) * 288 && t < OO * CC * 9;
             t += 256) {
            if (t < OO * CC * 9) {
                int o = t / (CC * 9);
                int rem = t - o * (CC * 9);
                int c = rem / 9;
                int k = rem - c * 9;
                int s = c >> 4, ci = c & 15;
                g_wprep[((((k * 32 + o) * 2 + s) * 4 + (ci >> 2)) * 4) + (ci & 3)] =
                    __float2half(w[t]);
            }
        }
    }

    const float sigma = *sigp;
    float wv[5];
    float s = 0.f;
#pragma unroll
    for (int i = 0; i < 5; i++) {
        float cc = (float)(i - 2);
        wv[i] = expf(-cc * cc / (2.f * sigma * sigma));
        s += wv[i];
    }
    const float inv_s2 = 1.f / (s * s);
    ull wp[5];
#pragma unroll
    for (int i = 0; i < 5; i++) wp[i] = pack2(wv[i], wv[i]);
    const ull invp = pack2(inv_s2, inv_s2);

    const int b = z >> 1;
    const int g16 = z & 1;
    const int gy0 = blockIdx.y * 32 - 2;
    const int gx0 = blockIdx.x * 32 - 2;

    for (int cp2 = 0; cp2 < 8; cp2++) {
        __syncthreads();
        const int c0 = g16 * 16 + 2 * cp2;
        const float* xp0 = x + ((size_t)b * CC + c0) * (HH * WW);
        const float* xp1 = xp0 + (HH * WW);

        for (int idx = tid; idx < 36 * 36; idx += 256) {
            int r = idx / 36, q = idx - r * 36;
            int gy = gy0 + r, gx = gx0 + q;
            float lo = 0.f, hi = 0.f;
            if (gy >= 0 && gy < HH && gx >= 0 && gx < WW) {
                lo = xp0[gy * WW + gx];
                hi = xp1[gy * WW + gx];
            }
            tile2[r * 36 + q] = pack2(lo, hi);
        }
        __syncthreads();

        for (int idx = tid; idx < 36 * 32; idx += 256) {
            int r = idx >> 5, q = idx & 31;
            ull a = mul2(wp[0], tile2[r * 36 + q]);
#pragma unroll
            for (int j = 1; j < 5; j++) a = fma2(wp[j], tile2[r * 36 + q + j], a);
            hbuf[idx] = a;
        }
        __syncthreads();

#pragma unroll
        for (int ry = 0; ry < 4; ry++) {
            const int row = threadIdx.y + ry * 8;
            ull a = mul2(wp[0], hbuf[row * 32 + threadIdx.x]);
#pragma unroll
            for (int i = 1; i < 5; i++)
                a = fma2(wp[i], hbuf[(row + i) * 32 + threadIdx.x], a);
            a = mul2(a, invp);
            float lo, hi;
            unpack2(a, lo, hi);
            obuf[cp2 * 1024 + row * 32 + threadIdx.x] = __floats2half2_rn(lo, hi);
        }
    }
    __syncthreads();

    // write-out: per px 32B slice at [px*32 + g16*16] halfs (full sectors)
    __half* gb = g_blur + (size_t)b * (HH * WW * 32);
    for (int i = tid; i < 2048; i += 256) {
        const int h = i & 1;
        const int px = i >> 1;
        uint32_t v[4];
#pragma unroll
        for (int j = 0; j < 4; j++)
            v[j] = *(const uint32_t*)&obuf[(4 * h + j) * 1024 + px];
        const int y = px >> 5, xg = px & 31;
        const size_t ga = ((size_t)(gy0 + 2 + y) * WW + (gx0 + 2 + xg)) * 32
                        + g16 * 16 + h * 8;
        *(uint4*)(gb + ga) = make_uint4(v[0], v[1], v[2], v[3]);
    }
}

// --------- Kernel 2: deformable conv, f16 mma.sync, single 32-ch tile --------------
__global__ __launch_bounds__(256, 2) void deform_kernel(const float* __restrict__ sigp,
                                                        float* __restrict__ out) {
    extern __shared__ __align__(16) char smem[];
    __half* tile = (__half*)smem;                    // [30 y][46 x][32 ch]
    ull* swf = (ull*)(smem + SWF_OFF);               // [9][32 och][2 ks][4 tig]
    int* geom = (int*)(smem + GEOM_OFF);             // 9 x {iy,ix,ipure,pad,4x half2w}
    const uint32_t tile_u = s2u(smem);

    const int tid = threadIdx.x;
    const int warp = tid >> 5;
    const int lane = tid & 31;
    const int g = lane >> 2;
    const int tig = lane & 3;

    const int b = blockIdx.z;
    const int by0 = blockIdx.y * TR;
    const int bx0 = blockIdx.x * TC;

    // stage weights
    {
        const uint4* src = (const uint4*)g_wprep;
        uint4* dst = (uint4*)swf;
        for (int i = tid; i < SWF_BYTES / 16; i += 256) dst[i] = src[i];
    }
    // tap geometry once
    if (tid < 9) {
        const float sigrate = (*sigp) * 6.0f;
        const int kyi = tid / 3 - 1;
        const int kxi = tid % 3 - 1;
        const float n2 = (float)(kyi * kyi + kxi * kxi);
        const float invn = (n2 > 0.f) ? (1.0f / sqrtf(n2)) : 0.0f;
        const float Dy = (float)kyi + sigrate * ((float)kyi * invn);
        const float Dx = (float)kxi + sigrate * ((float)kxi * invn);
        const float fy = floorf(Dy), fx = floorf(Dx);
        int iy = (int)fy, ix = (int)fx;
        const float ty = Dy - fy, tx = Dx - fx;
        const int pure = (tx == 0.f && ty == 0.f) ? 1 : 0;
        const int hi = pure ? 7 : 6;            // frac path reads +1 row/col
        iy = max(-7, min(iy, hi));
        ix = max(-7, min(ix, hi));
        int* gm = geom + tid * 8;
        gm[0] = iy;
        gm[1] = ix;
        gm[2] = pure;
        __half2* gw = (__half2*)(gm + 4);
        gw[0] = __half2half2(__float2half((1.f - ty) * (1.f - tx)));
        gw[1] = __half2half2(__float2half((1.f - ty) * tx));
        gw[2] = __half2half2(__float2half(ty * (1.f - tx)));
        gw[3] = __half2half2(__float2half(ty * tx));
    }

    float acc[2][2][4][4];
#pragma unroll
    for (int rr = 0; rr < 2; rr++)
#pragma unroll
        for (int cc = 0; cc < 2; cc++)
#pragma unroll
            for (int nt = 0; nt < 4; nt++)
#pragma unroll
                for (int j = 0; j < 4; j++) acc[rr][cc][nt][j] = 0.f;

    // stage full 32-ch tile via cp.async (zero-fill outside image)
    const __half* gp = g_blur + (size_t)b * (HH * WW * 32);
    for (int i = tid; i < ROWS * COLS * 4; i += 256) {
        const int q = i & 3;
        const int px = i >> 2;
        const int y = px / COLS;
        const int xx = px - y * COLS;
        const int gy = by0 - 7 + y;
        const int gx = bx0 - 7 + xx;
        const int inb = (gy >= 0 && gy < HH && gx >= 0 && gx < WW) ? 16 : 0;
        cpasync16(tile_u + i * 16, gp + ((size_t)gy * WW + gx) * 32 + q * 8, inb);
    }
    asm volatile("cp.async.commit_group;");
    asm volatile("cp.async.wait_group 0;" ::: "memory");
    __syncthreads();

    for (int tap = 0; tap < 9; tap++) {
        const int* gm = geom + tap * 8;
        const int iy = gm[0], ix = gm[1], ipure = gm[2];
        const __half2* gw = (const __half2*)(gm + 4);
        const __half2 a00 = gw[0], a01 = gw[1], a10 = gw[2], a11 = gw[3];

#pragma unroll
        for (int ks = 0; ks < 2; ks++) {
            // B fragments: one LDS.64 per nt
            ull bv[4];
            const ull* wb = swf + (tap * 32) * 8 + ks * 4 + tig;
#pragma unroll
            for (int nt = 0; nt < 4; nt++) bv[nt] = wb[(nt * 8 + g) * 8];

#pragma unroll
            for (int rr = 0; rr < 2; rr++) {
#pragma unroll
                for (int cc = 0; cc < 2; cc++) {
                    const int row = 2 * warp + rr + iy + 7;
                    const int col = cc * 16 + g + ix + 7;
                    const __half* p0 = tile + ((size_t)row * COLS + col) * PXH
                                     + ks * 16 + tig * 4;
                    ull vm, vm8;
                    if (ipure) {
                        vm = *(const ull*)p0;
                        vm8 = *(const ull*)(p0 + 8 * PXH);
                    } else {
#pragma unroll
                        for (int m = 0; m < 2; m++) {
                            const __half* p = p0 + m * 8 * PXH;
                            const ull u00 = *(const ull*)p;
                            const ull u01 = *(const ull*)(p + PXH);
                            const ull u10 = *(const ull*)(p + COLS * PXH);
                            const ull u11 = *(const ull*)(p + COLS * PXH + PXH);
                            __half2 lo = __hmul2(a00, *(const __half2*)&u00);
                            lo = __hfma2(a01, *(const __half2*)&u01, lo);
                            lo = __hfma2(a10, *(const __half2*)&u10, lo);
                            lo = __hfma2(a11, *(const __half2*)&u11, lo);
                            __half2 hi = __hmul2(a00, ((const __half2*)&u00)[1]);
                            hi = __hfma2(a01, ((const __half2*)&u01)[1], hi);
                            hi = __hfma2(a10, ((const __half2*)&u10)[1], hi);
                            hi = __hfma2(a11, ((const __half2*)&u11)[1], hi);
                            ull r = ((ull)*(uint32_t*)&hi << 32) | *(uint32_t*)&lo;
                            if (m == 0) vm = r; else vm8 = r;
                        }
                    }
                    const uint32_t A0 = (uint32_t)vm;
                    const uint32_t A2 = (uint32_t)(vm >> 32);
                    const uint32_t A1 = (uint32_t)vm8;
                    const uint32_t A3 = (uint32_t)(vm8 >> 32);
#pragma unroll
                    for (int nt = 0; nt < 4; nt++)
                        mma_f16(acc[rr][cc][nt], A0, A1, A2, A3,
                                (uint32_t)bv[nt], (uint32_t)(bv[nt] >> 32));
                }
            }
        }
    }

    // epilogue (mapping identical to R9 passing kernel)
#pragma unroll
    for (int rr = 0; rr < 2; rr++) {
        const int gy = by0 + 2 * warp + rr;
        float* ob = out + (size_t)b * OO * (HH * WW) + (size_t)gy * WW + bx0;
#pragma unroll
        for (int cc = 0; cc < 2; cc++) {
            float* oc = ob + cc * 16 + g;
#pragma unroll
            for (int nt = 0; nt < 4; nt++) {
                const int och = nt * 8 + 2 * tig;
                float* p0 = oc + (size_t)och * (HH * WW);
                float* p1 = p0 + (size_t)(HH * WW);
                p0[0] = acc[rr][cc][nt][0];
                p1[0] = acc[rr][cc][nt][1];
                p0[8] = acc[rr][cc][nt][2];
                p1[8] = acc[rr][cc][nt][3];
            }
        }
    }
}

extern "C" void kernel_launch(void* const* d_in, const int* in_sizes, int n_in,
                              void* d_out, int out_size) {
    const float* x = nullptr;
    const float* sig = nullptr;
    const float* wgt = nullptr;
    for (int i = 0; i < n_in; i++) {
        if (in_sizes[i] == 1) sig = (const float*)d_in[i];
        else if (in_sizes[i] == OO * CC * 9) wgt = (const float*)d_in[i];
        else x = (const float*)d_in[i];
    }
    float* out = (float*)d_out;

    cudaFuncSetAttribute(blur_kernel,
                         cudaFuncAttributeMaxDynamicSharedMemorySize, B_SMEM_DYN);
    dim3 bgrid(WW / 32, HH / 32, BB * 2);
    blur_kernel<<<bgrid, dim3(32, 8), B_SMEM_DYN>>>(x, sig, wgt);

    cudaFuncSetAttribute(deform_kernel,
                         cudaFuncAttributeMaxDynamicSharedMemorySize, SMEM_DYN);
    dim3 dgrid(WW / TC, HH / TR, BB);
    deform_kernel<<<dgrid, 256, SMEM_DYN>>>(sig, out);
}

// round 11
// speedup vs baseline: 1.2968x; 1.2968x over previous
#include <cuda_runtime.h>
#include <cuda_fp16.h>
#include <cstdint>

#define HH 256
#define WW 256
#define BB 16
#define CC 32
#define OO 32
#define TR 16
#define TC 32

#define ROWS 30                      // tile y: exact reach
#define COLS 46                      // tile x: exact reach
#define PLANE_H (ROWS * COLS * 16)   // 22080 halfs per ks-plane (44160 B, %128==0)
#define TILE_BYTES (2 * PLANE_H * 2)             // 88320
#define SWF_OFF  TILE_BYTES
#define SWF_BYTES (9 * 2 * 32 * 4 * 8)           // 18432: [tap][ks][och][tig] ull
#define GEOM_OFF (SWF_OFF + SWF_BYTES)           // 106752
#define SMEM_DYN (GEOM_OFF + 9 * 32)             // 107040 (2 CTAs/SM)

// blur dynamic smem: tile2 (36*36 ull) + hbuf (36*32 ull) + obuf (4*1024 half2)
#define B_TILE2_ULL (36 * 36)
#define B_HBUF_ULL  (36 * 32)
#define B_OBUF_OFF  ((B_TILE2_ULL + B_HBUF_ULL) * 8)     // 19584
#define B_SMEM_DYN  (B_OBUF_OFF + 4 * 1024 * 4)          // 35968

// g_blur: [b][y][x][32 ch] halfs
__device__ __half g_blur[(size_t)BB * HH * WW * 32];
__device__ __half g_wprep[9 * 2 * 32 * 4 * 4];   // ull layout [tap][ks][och][tig]

typedef unsigned long long ull;

__device__ __forceinline__ ull pack2(float lo, float hi) {
    ull r; asm("mov.b64 %0, {%1, %2};" : "=l"(r) : "f"(lo), "f"(hi)); return r;
}
__device__ __forceinline__ void unpack2(ull v, float& lo, float& hi) {
    asm("mov.b64 {%0, %1}, %2;" : "=f"(lo), "=f"(hi) : "l"(v));
}
__device__ __forceinline__ ull fma2(ull a, ull b, ull c) {
    ull d; asm("fma.rn.f32x2 %0, %1, %2, %3;" : "=l"(d) : "l"(a), "l"(b), "l"(c));
    return d;
}
__device__ __forceinline__ ull mul2(ull a, ull b) {
    ull d; asm("mul.rn.f32x2 %0, %1, %2;" : "=l"(d) : "l"(a), "l"(b)); return d;
}
__device__ __forceinline__ uint32_t s2u(const void* p) {
    uint32_t a;
    asm("{ .reg .u64 t; cvta.to.shared.u64 t, %1; cvt.u32.u64 %0, t; }"
        : "=r"(a) : "l"(p));
    return a;
}
__device__ __forceinline__ void cpasync16(uint32_t dst, const void* src, int sz) {
    asm volatile("cp.async.cg.shared.global [%0], [%1], 16, %2;"
                 :: "r"(dst), "l"(src), "r"(sz) : "memory");
}
__device__ __forceinline__ void mma_f16(float* d, uint32_t a0, uint32_t a1,
                                        uint32_t a2, uint32_t a3,
                                        uint32_t b0, uint32_t b1) {
    asm volatile(
        "mma.sync.aligned.m16n8k16.row.col.f32.f16.f16.f32 "
        "{%0,%1,%2,%3}, {%4,%5,%6,%7}, {%8,%9}, {%0,%1,%2,%3};"
        : "+f"(d[0]), "+f"(d[1]), "+f"(d[2]), "+f"(d[3])
        : "r"(a0), "r"(a1), "r"(a2), "r"(a3), "r"(b0), "r"(b1));
}

// --------- Kernel 1: separable 5x5 blur (8 ch/block) + folded weight prep ----------
// grid (8,8,BB*4): z = b*4 + q8 -> channels q8*8..+7. Blocks x==0,y==0 prep weights.
__global__ __launch_bounds__(256) void blur_kernel(const float* __restrict__ x,
                                                   const float* __restrict__ sigp,
                                                   const float* __restrict__ w) {
    extern __shared__ __align__(16) char bsm[];
    ull* tile2 = (ull*)bsm;                          // [36][36]
    ull* hbuf = tile2 + B_TILE2_ULL;                 // [36][32]
    __half2* obuf = (__half2*)(bsm + B_OBUF_OFF);    // [4 pair][1024 px]

    const int tid = threadIdx.x + threadIdx.y * 32;
    const int z = blockIdx.z;

    // folded weight prep: [o][c][k] -> half [(tap*2+s)*32+o][tig][j]
    if (blockIdx.x == 0 && blockIdx.y == 0) {
        for (int t = z * 144 + tid; t < (z + 1) * 144; t += 256) {
            if (t < OO * CC * 9) {
                int o = t / (CC * 9);
                int rem = t - o * (CC * 9);
                int c = rem / 9;
                int k = rem - c * 9;
                int s = c >> 4, ci = c & 15;
                g_wprep[((((k * 2 + s) * 32 + o) * 4 + (ci >> 2)) * 4) + (ci & 3)] =
                    __float2half(w[t]);
            }
        }
    }

    const float sigma = *sigp;
    float wv[5];
    float s = 0.f;
#pragma unroll
    for (int i = 0; i < 5; i++) {
        float cc = (float)(i - 2);
        wv[i] = expf(-cc * cc / (2.f * sigma * sigma));
        s += wv[i];
    }
    const float inv_s2 = 1.f / (s * s);
    ull wp[5];
#pragma unroll
    for (int i = 0; i < 5; i++) wp[i] = pack2(wv[i], wv[i]);
    const ull invp = pack2(inv_s2, inv_s2);

    const int b = z >> 2;
    const int q8 = z & 3;
    const int gy0 = blockIdx.y * 32 - 2;
    const int gx0 = blockIdx.x * 32 - 2;

    for (int cp2 = 0; cp2 < 4; cp2++) {
        __syncthreads();
        const int c0 = q8 * 8 + 2 * cp2;
        const float* xp0 = x + ((size_t)b * CC + c0) * (HH * WW);
        const float* xp1 = xp0 + (HH * WW);

        for (int idx = tid; idx < 36 * 36; idx += 256) {
            int r = idx / 36, q = idx - r * 36;
            int gy = gy0 + r, gx = gx0 + q;
            float lo = 0.f, hi = 0.f;
            if (gy >= 0 && gy < HH && gx >= 0 && gx < WW) {
                lo = xp0[gy * WW + gx];
                hi = xp1[gy * WW + gx];
            }
            tile2[r * 36 + q] = pack2(lo, hi);
        }
        __syncthreads();

        for (int idx = tid; idx < 36 * 32; idx += 256) {
            int r = idx >> 5, q = idx & 31;
            ull a = mul2(wp[0], tile2[r * 36 + q]);
#pragma unroll
            for (int j = 1; j < 5; j++) a = fma2(wp[j], tile2[r * 36 + q + j], a);
            hbuf[idx] = a;
        }
        __syncthreads();

#pragma unroll
        for (int ry = 0; ry < 4; ry++) {
            const int row = threadIdx.y + ry * 8;
            ull a = mul2(wp[0], hbuf[row * 32 + threadIdx.x]);
#pragma unroll
            for (int i = 1; i < 5; i++)
                a = fma2(wp[i], hbuf[(row + i) * 32 + threadIdx.x], a);
            a = mul2(a, invp);
            float lo, hi;
            unpack2(a, lo, hi);
            obuf[cp2 * 1024 + row * 32 + threadIdx.x] = __floats2half2_rn(lo, hi);
        }
    }
    __syncthreads();

    // write-out: one uint4 (8 ch) per pixel, coalesced 16B stores
    __half* gb = g_blur + (size_t)b * (HH * WW * 32);
    for (int px = tid; px < 1024; px += 256) {
        uint32_t v[4];
#pragma unroll
        for (int j = 0; j < 4; j++)
            v[j] = *(const uint32_t*)&obuf[j * 1024 + px];
        const int y = px >> 5, xg = px & 31;
        const size_t ga = ((size_t)(gy0 + 2 + y) * WW + (gx0 + 2 + xg)) * 32 + q8 * 8;
        *(uint4*)(gb + ga) = make_uint4(v[0], v[1], v[2], v[3]);
    }
}

// --------- Kernel 2: deformable conv, f16 mma.sync, two ch16 planes ----------------
__global__ __launch_bounds__(256, 2) void deform_kernel(const float* __restrict__ sigp,
                                                        float* __restrict__ out) {
    extern __shared__ __align__(16) char smem[];
    __half* tile = (__half*)smem;                    // [2 ks][30 y][46 x][16 ch]
    ull* swf = (ull*)(smem + SWF_OFF);               // [9 tap][2 ks][32 och][4 tig]
    int* geom = (int*)(smem + GEOM_OFF);             // 9 x {iy,ix,ipure,pad,4x half2w}
    const uint32_t tile_u = s2u(smem);

    const int tid = threadIdx.x;
    const int warp = tid >> 5;
    const int lane = tid & 31;
    const int g = lane >> 2;
    const int tig = lane & 3;

    const int b = blockIdx.z;
    const int by0 = blockIdx.y * TR;
    const int bx0 = blockIdx.x * TC;

    // stage weights
    {
        const uint4* src = (const uint4*)g_wprep;
        uint4* dst = (uint4*)swf;
        for (int i = tid; i < SWF_BYTES / 16; i += 256) dst[i] = src[i];
    }
    // tap geometry once
    if (tid < 9) {
        const float sigrate = (*sigp) * 6.0f;
        const int kyi = tid / 3 - 1;
        const int kxi = tid % 3 - 1;
        const float n2 = (float)(kyi * kyi + kxi * kxi);
        const float invn = (n2 > 0.f) ? (1.0f / sqrtf(n2)) : 0.0f;
        const float Dy = (float)kyi + sigrate * ((float)kyi * invn);
        const float Dx = (float)kxi + sigrate * ((float)kxi * invn);
        const float fy = floorf(Dy), fx = floorf(Dx);
        int iy = (int)fy, ix = (int)fx;
        const float ty = Dy - fy, tx = Dx - fx;
        const int pure = (tx == 0.f && ty == 0.f) ? 1 : 0;
        const int hi = pure ? 7 : 6;
        iy = max(-7, min(iy, hi));
        ix = max(-7, min(ix, hi));
        int* gm = geom + tid * 8;
        gm[0] = iy;
        gm[1] = ix;
        gm[2] = pure;
        __half2* gw = (__half2*)(gm + 4);
        gw[0] = __half2half2(__float2half((1.f - ty) * (1.f - tx)));
        gw[1] = __half2half2(__float2half((1.f - ty) * tx));
        gw[2] = __half2half2(__float2half(ty * (1.f - tx)));
        gw[3] = __half2half2(__float2half(ty * tx));
    }

    float acc[2][2][4][4];
#pragma unroll
    for (int rr = 0; rr < 2; rr++)
#pragma unroll
        for (int cc = 0; cc < 2; cc++)
#pragma unroll
            for (int nt = 0; nt < 4; nt++)
#pragma unroll
                for (int j = 0; j < 4; j++) acc[rr][cc][nt][j] = 0.f;

    // stage full tile via cp.async into two ks-planes (zero-fill outside image)
    const __half* gp = g_blur + (size_t)b * (HH * WW * 32);
    for (int i = tid; i < ROWS * COLS * 4; i += 256) {
        const int q = i & 3;             // ks = q>>1, h = q&1
        const int ks = q >> 1, h = q & 1;
        const int px = i >> 2;
        const int y = px / COLS;
        const int xx = px - y * COLS;
        const int gy = by0 - 7 + y;
        const int gx = bx0 - 7 + xx;
        const int inb = (gy >= 0 && gy < HH && gx >= 0 && gx < WW) ? 16 : 0;
        const uint32_t dst = tile_u + (ks * PLANE_H + px * 16 + h * 8) * 2;
        cpasync16(dst, gp + ((size_t)gy * WW + gx) * 32 + ks * 16 + h * 8, inb);
    }
    asm volatile("cp.async.commit_group;");
    asm volatile("cp.async.wait_group 0;" ::: "memory");
    __syncthreads();

    for (int tap = 0; tap < 9; tap++) {
        const int* gm = geom + tap * 8;
        const int iy = gm[0], ix = gm[1], ipure = gm[2];
        const __half2* gw = (const __half2*)(gm + 4);
        const __half2 a00 = gw[0], a01 = gw[1], a10 = gw[2], a11 = gw[3];

#pragma unroll
        for (int ks = 0; ks < 2; ks++) {
            // B fragments: one conflict-free LDS.64 per nt
            ull bv[4];
            const ull* wb = swf + (tap * 2 + ks) * 128 + tig;
#pragma unroll
            for (int nt = 0; nt < 4; nt++) bv[nt] = wb[(nt * 8 + g) * 4];

            const __half* plane = tile + ks * PLANE_H;
#pragma unroll
            for (int rr = 0; rr < 2; rr++) {
#pragma unroll
                for (int cc = 0; cc < 2; cc++) {
                    const int row = 2 * warp + rr + iy + 7;
                    const int col = cc * 16 + g + ix + 7;
                    const __half* p0 = plane + ((size_t)row * COLS + col) * 16
                                     + tig * 4;
                    ull vm, vm8;
                    if (ipure) {
                        vm = *(const ull*)p0;
                        vm8 = *(const ull*)(p0 + 8 * 16);
                    } else {
#pragma unroll
                        for (int m = 0; m < 2; m++) {
                            const __half* p = p0 + m * 8 * 16;
                            const ull u00 = *(const ull*)p;
                            const ull u01 = *(const ull*)(p + 16);
                            const ull u10 = *(const ull*)(p + COLS * 16);
                            const ull u11 = *(const ull*)(p + COLS * 16 + 16);
                            __half2 lo = __hmul2(a00, *(const __half2*)&u00);
                            lo = __hfma2(a01, *(const __half2*)&u01, lo);
                            lo = __hfma2(a10, *(const __half2*)&u10, lo);
                            lo = __hfma2(a11, *(const __half2*)&u11, lo);
                            __half2 hi = __hmul2(a00, ((const __half2*)&u00)[1]);
                            hi = __hfma2(a01, ((const __half2*)&u01)[1], hi);
                            hi = __hfma2(a10, ((const __half2*)&u10)[1], hi);
                            hi = __hfma2(a11, ((const __half2*)&u11)[1], hi);
                            ull r = ((ull)*(uint32_t*)&hi << 32) | *(uint32_t*)&lo;
                            if (m == 0) vm = r; else vm8 = r;
                        }
                    }
                    const uint32_t A0 = (uint32_t)vm;
                    const uint32_t A2 = (uint32_t)(vm >> 32);
                    const uint32_t A1 = (uint32_t)vm8;
                    const uint32_t A3 = (uint32_t)(vm8 >> 32);
#pragma unroll
                    for (int nt = 0; nt < 4; nt++)
                        mma_f16(acc[rr][cc][nt], A0, A1, A2, A3,
                                (uint32_t)bv[nt], (uint32_t)(bv[nt] >> 32));
                }
            }
        }
    }

    // epilogue (mapping identical to prior passing kernels)
#pragma unroll
    for (int rr = 0; rr < 2; rr++) {
        const int gy = by0 + 2 * warp + rr;
        float* ob = out + (size_t)b * OO * (HH * WW) + (size_t)gy * WW + bx0;
#pragma unroll
        for (int cc = 0; cc < 2; cc++) {
            float* oc = ob + cc * 16 + g;
#pragma unroll
            for (int nt = 0; nt < 4; nt++) {
                const int och = nt * 8 + 2 * tig;
                float* p0 = oc + (size_t)och * (HH * WW);
                float* p1 = p0 + (size_t)(HH * WW);
                p0[0] = acc[rr][cc][nt][0];
                p1[0] = acc[rr][cc][nt][1];
                p0[8] = acc[rr][cc][nt][2];
                p1[8] = acc[rr][cc][nt][3];
            }
        }
    }
}

extern "C" void kernel_launch(void* const* d_in, const int* in_sizes, int n_in,
                              void* d_out, int out_size) {
    const float* x = nullptr;
    const float* sig = nullptr;
    const float* wgt = nullptr;
    for (int i = 0; i < n_in; i++) {
        if (in_sizes[i] == 1) sig = (const float*)d_in[i];
        else if (in_sizes[i] == OO * CC * 9) wgt = (const float*)d_in[i];
        else x = (const float*)d_in[i];
    }
    float* out = (float*)d_out;

    cudaFuncSetAttribute(blur_kernel,
                         cudaFuncAttributeMaxDynamicSharedMemorySize, B_SMEM_DYN);
    dim3 bgrid(WW / 32, HH / 32, BB * 4);
    blur_kernel<<<bgrid, dim3(32, 8), B_SMEM_DYN>>>(x, sig, wgt);

    cudaFuncSetAttribute(deform_kernel,
                         cudaFuncAttributeMaxDynamicSharedMemorySize, SMEM_DYN);
    dim3 dgrid(WW / TC, HH / TR, BB);
    deform_kernel<<<dgrid, 256, SMEM_DYN>>>(sig, out);
}